// round 11
// baseline (speedup 1.0000x reference)
#include <cuda_runtime.h>
#include <cuda_fp16.h>
#include <cstdint>
#include <math.h>

#define BATCH 4
#define SEQ   2048
#define HID   2048
#define INTER 5504
#define MTOK  (BATCH*SEQ)            // 8192
#define OUT_ELEMS ((long)MTOK*HID)   // 16777216

// ---------------- scratch ----------------
__device__ __half g_Xh [(long)MTOK*HID];
__device__ __half g_Wgh[(long)INTER*HID];
__device__ __half g_Wuh[(long)INTER*HID];
__device__ __half g_Wdh[(long)HID*INTER];
__device__ __half g_inter[(long)MTOK*INTER];
__device__ float  g_rowsq[INTER];
__device__ float  g_s[BATCH*INTER];      // impacts accumulator (atomicAdd)

// ---------------- helpers ----------------
__device__ __forceinline__ uint32_t smem_u32(const void* p){
    uint32_t a;
    asm("{ .reg .u64 t; cvta.to.shared.u64 t, %1; cvt.u32.u64 %0, t; }" : "=r"(a) : "l"(p));
    return a;
}
__device__ __forceinline__ void cpa16(uint32_t dst, const void* src){
    asm volatile("cp.async.cg.shared.global [%0], [%1], 16;" :: "r"(dst), "l"(src));
}
__device__ __forceinline__ void ldsm4(uint32_t r[4], uint32_t addr){
    asm volatile("ldmatrix.sync.aligned.m8n8.x4.shared.b16 {%0,%1,%2,%3}, [%4];"
                 : "=r"(r[0]), "=r"(r[1]), "=r"(r[2]), "=r"(r[3]) : "r"(addr));
}
__device__ __forceinline__ void mma_f16(float c[4],
                                        uint32_t a0, uint32_t a1, uint32_t a2, uint32_t a3,
                                        uint32_t b0, uint32_t b1) {
    asm volatile(
        "mma.sync.aligned.m16n8k16.row.col.f32.f16.f16.f32 "
        "{%0,%1,%2,%3}, {%4,%5,%6,%7}, {%8,%9}, {%0,%1,%2,%3};"
        : "+f"(c[0]), "+f"(c[1]), "+f"(c[2]), "+f"(c[3])
        : "r"(a0), "r"(a1), "r"(a2), "r"(a3), "r"(b0), "r"(b1));
}
#define CP_COMMIT() asm volatile("cp.async.commit_group;" ::: "memory")
#define CP_WAIT(n)  asm volatile("cp.async.wait_group %0;" :: "n"(n) : "memory")

// 128B-row XOR swizzle (conflict-free)
#define SWZB(o) ((o) ^ (((o) >> 3) & 0x70))

// ============================================================================
// Fused gate/up GEMM + SwiGLU + impacts partial reduction.
// Block 128m x 64n, 8 warps (2m x 4n), warp 64m x 16n per mat.
// 3 stages x 32KB = 96KB -> 2 CTAs/SM. Mainloop unrolled by 3.
// ============================================================================
#define GU_STAGE_B 32768
#define GU_BG_OFF  16384
#define GU_BU_OFF  24576
#define GU_SMEM_BYTES (3*GU_STAGE_B)   // 98304

__global__ void __launch_bounds__(256,2)
gemm_gu(const __half* __restrict__ X, const __half* __restrict__ Wg,
        const __half* __restrict__ Wu, __half* __restrict__ inter,
        float* __restrict__ spart)
{
    extern __shared__ char smemc[];
    const uint32_t sb = smem_u32(smemc);

    const int tid  = threadIdx.x;
    const int wid  = tid >> 5;
    const int lane = tid & 31;
    const int grp  = lane >> 2;
    const int tig  = lane & 3;
    const int wm   = wid >> 2;    // 0..1
    const int wn   = wid & 3;     // 0..3

    const int NBN = INTER/64;     // 86
    const int GM  = 16;
    int bid = blockIdx.x;
    int g   = bid / (GM*NBN);
    int r   = bid % (GM*NBN);
    const long bm = (long)(g*GM + (r % GM)) * 128;
    const int  bn = (r / GM) * 64;

    const int ldr = tid >> 3;        // 0..31
    const int ldc = tid & 7;         // 0..7 (16B units)

    const __half* Ag = X  + (bm + ldr)*(long)HID + ldc*8;
    const __half* Gg = Wg + (long)(bn + ldr)*HID + ldc*8;
    const __half* Ug = Wu + (long)(bn + ldr)*HID + ldc*8;

    float acc_g[4][2][4], acc_u[4][2][4];
#pragma unroll
    for (int mi = 0; mi < 4; mi++)
#pragma unroll
        for (int ni = 0; ni < 2; ni++)
#pragma unroll
            for (int q = 0; q < 4; q++) { acc_g[mi][ni][q] = 0.f; acc_u[mi][ni][q] = 0.f; }

    uint32_t stoffA[4];
#pragma unroll
    for (int i = 0; i < 4; i++)
        stoffA[i] = SWZB((uint32_t)((ldr + 32*i)*128 + ldc*16));
    uint32_t stoffB[2];
#pragma unroll
    for (int i = 0; i < 2; i++)
        stoffB[i] = SWZB((uint32_t)((ldr + 32*i)*128 + ldc*16));

    // ldmatrix per-lane geometry (hoisted XOR terms)
    const uint32_t swzm = (lane & 7) * 16;
    const uint32_t browA = (wm*64 + (lane & 15)) * 128;
    const uint32_t akbe = ((lane >> 4) & 1) * 16;
    const uint32_t browB = (wn*16 + ((lane >> 4) & 1)*8 + (lane & 7)) * 128;
    const uint32_t bkbe = ((lane >> 3) & 1) * 16;
    uint32_t akb_r[4], bkb_r[4];
#pragma unroll
    for (int ks = 0; ks < 4; ks++) {
        akb_r[ks] = ((uint32_t)(ks*32) + akbe) ^ swzm;
        bkb_r[ks] = ((uint32_t)(ks*32) + bkbe) ^ swzm;
    }

    const int nK = HID/64;   // 32

    // preload chunks 0,1 into stages 0,1
#pragma unroll
    for (int p = 0; p < 2; p++) {
        const int k0 = p*64;
        const uint32_t st = sb + p*GU_STAGE_B;
#pragma unroll
        for (int i = 0; i < 4; i++)
            cpa16(st + stoffA[i], Ag + (long)i*32*HID + k0);
#pragma unroll
        for (int i = 0; i < 2; i++) {
            cpa16(st + GU_BG_OFF + stoffB[i], Gg + (long)i*32*HID + k0);
            cpa16(st + GU_BU_OFF + stoffB[i], Ug + (long)i*32*HID + k0);
        }
        CP_COMMIT();
    }

#define GU_BODY(SS)                                                            \
    {                                                                          \
        CP_WAIT(1);                                                            \
        __syncthreads();                                                       \
        if (j + 2 < nK) {                                                      \
            const int k0 = (j+2)*64;                                           \
            const uint32_t st = sb + (((SS)+2)%3)*GU_STAGE_B;                  \
            _Pragma("unroll")                                                  \
            for (int i = 0; i < 4; i++)                                        \
                cpa16(st + stoffA[i], Ag + (long)i*32*HID + k0);               \
            _Pragma("unroll")                                                  \
            for (int i = 0; i < 2; i++) {                                      \
                cpa16(st + GU_BG_OFF + stoffB[i], Gg + (long)i*32*HID + k0);   \
                cpa16(st + GU_BU_OFF + stoffB[i], Ug + (long)i*32*HID + k0);   \
            }                                                                  \
        }                                                                      \
        CP_COMMIT();                                                           \
        const uint32_t As = sb + (SS)*GU_STAGE_B;                              \
        const uint32_t Gs = As + GU_BG_OFF;                                    \
        const uint32_t Us = As + GU_BU_OFF;                                    \
        _Pragma("unroll")                                                      \
        for (int ks = 0; ks < 4; ks++) {                                       \
            uint32_t af[4][4], bg[4], bu[4];                                   \
            _Pragma("unroll")                                                  \
            for (int mi = 0; mi < 4; mi++)                                     \
                ldsm4(af[mi], As + browA + mi*2048 + akb_r[ks]);               \
            ldsm4(bg, Gs + browB + bkb_r[ks]);                                 \
            ldsm4(bu, Us + browB + bkb_r[ks]);                                 \
            _Pragma("unroll")                                                  \
            for (int mi = 0; mi < 4; mi++)                                     \
                _Pragma("unroll")                                              \
                for (int ni = 0; ni < 2; ni++) {                               \
                    mma_f16(acc_g[mi][ni], af[mi][0], af[mi][1], af[mi][2],    \
                            af[mi][3], bg[ni*2], bg[ni*2+1]);                  \
                    mma_f16(acc_u[mi][ni], af[mi][0], af[mi][1], af[mi][2],    \
                            af[mi][3], bu[ni*2], bu[ni*2+1]);                  \
                }                                                              \
        }                                                                      \
        j++;                                                                   \
    }

    {
        int j = 0;
        while (j + 3 <= nK) { GU_BODY(0); GU_BODY(1); GU_BODY(2); }
        // nK % 3 == 2 tail (32 = 3*10 + 2), enters with j % 3 == 0
        GU_BODY(0); GU_BODY(1);
    }
#undef GU_BODY

    // epilogue: inter = half( silu(g) * u );  colsum += o^2 for impacts
    float cs[2][2] = {{0.f,0.f},{0.f,0.f}};   // [ni][col in pair]
#pragma unroll
    for (int mi = 0; mi < 4; mi++) {
#pragma unroll
        for (int ni = 0; ni < 2; ni++) {
            long r0 = bm + wm*64 + mi*16 + grp;
            long c0 = bn + wn*16 + ni*8 + tig*2;
            float gv, uv; __half2 h;
            gv = acc_g[mi][ni][0]; uv = acc_u[mi][ni][0];
            float o0 = (gv / (1.f + __expf(-gv))) * uv;
            gv = acc_g[mi][ni][1]; uv = acc_u[mi][ni][1];
            float o1 = (gv / (1.f + __expf(-gv))) * uv;
            h = __floats2half2_rn(o0, o1);
            *(__half2*)(inter + r0*INTER + c0) = h;
            gv = acc_g[mi][ni][2]; uv = acc_u[mi][ni][2];
            float o2 = (gv / (1.f + __expf(-gv))) * uv;
            gv = acc_g[mi][ni][3]; uv = acc_u[mi][ni][3];
            float o3 = (gv / (1.f + __expf(-gv))) * uv;
            h = __floats2half2_rn(o2, o3);
            *(__half2*)(inter + (r0+8)*INTER + c0) = h;
            cs[ni][0] += o0*o0 + o2*o2;
            cs[ni][1] += o1*o1 + o3*o3;
        }
    }
    // reduce over the 8 row-lane-groups (lanes differing in bits 2..4)
#pragma unroll
    for (int off = 4; off < 32; off <<= 1) {
#pragma unroll
        for (int ni = 0; ni < 2; ni++) {
            cs[ni][0] += __shfl_xor_sync(0xffffffffu, cs[ni][0], off);
            cs[ni][1] += __shfl_xor_sync(0xffffffffu, cs[ni][1], off);
        }
    }
    if (grp == 0) {
        const int b = (int)(bm >> 11);          // bm / SEQ
        float* sp = spart + b*INTER;
#pragma unroll
        for (int ni = 0; ni < 2; ni++) {
            int c0 = bn + wn*16 + ni*8 + tig*2;
            atomicAdd(&sp[c0],   cs[ni][0]);
            atomicAdd(&sp[c0+1], cs[ni][1]);
        }
    }
}

// ============================================================================
// Down GEMM fp16 + ldmatrix: out = inter * Wd^T, K=5504.
// Block 128m x 64n (same geometry as gemm_gu, single B) -> 2048 CTAs,
// ~6.9 waves at 2 CTAs/SM: kills the 13% wave-quantization of the 128x128 tile.
// Stage = A 16KB + B 8KB = 24KB; 3 stages = 72KB -> 2 CTAs/SM.
// ============================================================================
#define DN_STAGE_B 24576
#define DN_B_OFF   16384
#define DN_SMEM_BYTES (3*DN_STAGE_B)   // 73728

__global__ void __launch_bounds__(256,2)
gemm_down(const __half* __restrict__ A, const __half* __restrict__ B, float* __restrict__ C)
{
    extern __shared__ char smemc[];
    const uint32_t sb = smem_u32(smemc);

    const int tid  = threadIdx.x;
    const int wid  = tid >> 5;
    const int lane = tid & 31;
    const int grp  = lane >> 2;
    const int tig  = lane & 3;
    const int wm   = wid >> 2;    // 0..1
    const int wn   = wid & 3;     // 0..3

    const int NBN = HID/64;    // 32
    const int GM  = 16;
    int bid = blockIdx.x;
    int g   = bid / (GM*NBN);
    int r   = bid % (GM*NBN);
    const long bm = (long)(g*GM + (r % GM)) * 128;
    const int  bn = (r / GM) * 64;

    const int ldr = tid >> 3;
    const int ldc = tid & 7;

    const __half* Ag = A + (bm + ldr)*(long)INTER + ldc*8;
    const __half* Bg = B + (long)(bn + ldr)*INTER + ldc*8;

    float acc[4][2][4];
#pragma unroll
    for (int mi = 0; mi < 4; mi++)
#pragma unroll
        for (int ni = 0; ni < 2; ni++)
#pragma unroll
            for (int q = 0; q < 4; q++) acc[mi][ni][q] = 0.f;

    uint32_t stoffA[4];
#pragma unroll
    for (int i = 0; i < 4; i++)
        stoffA[i] = SWZB((uint32_t)((ldr + 32*i)*128 + ldc*16));
    uint32_t stoffB[2];
#pragma unroll
    for (int i = 0; i < 2; i++)
        stoffB[i] = SWZB((uint32_t)((ldr + 32*i)*128 + ldc*16));

    const uint32_t swzm = (lane & 7) * 16;
    const uint32_t browA = (wm*64 + (lane & 15)) * 128;
    const uint32_t akbe = ((lane >> 4) & 1) * 16;
    const uint32_t browB = (wn*16 + ((lane >> 4) & 1)*8 + (lane & 7)) * 128;
    const uint32_t bkbe = ((lane >> 3) & 1) * 16;
    uint32_t akb_r[4], bkb_r[4];
#pragma unroll
    for (int ks = 0; ks < 4; ks++) {
        akb_r[ks] = ((uint32_t)(ks*32) + akbe) ^ swzm;
        bkb_r[ks] = ((uint32_t)(ks*32) + bkbe) ^ swzm;
    }

    const int nK = INTER/64;   // 86

#pragma unroll
    for (int p = 0; p < 2; p++) {
        const int k0 = p*64;
        const uint32_t st = sb + p*DN_STAGE_B;
#pragma unroll
        for (int i = 0; i < 4; i++)
            cpa16(st + stoffA[i], Ag + (long)i*32*INTER + k0);
#pragma unroll
        for (int i = 0; i < 2; i++)
            cpa16(st + DN_B_OFF + stoffB[i], Bg + (long)i*32*INTER + k0);
        CP_COMMIT();
    }

#define DN_BODY(SS)                                                            \
    {                                                                          \
        CP_WAIT(1);                                                            \
        __syncthreads();                                                       \
        if (j + 2 < nK) {                                                      \
            const int k0 = (j+2)*64;                                           \
            const uint32_t st = sb + (((SS)+2)%3)*DN_STAGE_B;                  \
            _Pragma("unroll")                                                  \
            for (int i = 0; i < 4; i++)                                        \
                cpa16(st + stoffA[i], Ag + (long)i*32*INTER + k0);             \
            _Pragma("unroll")                                                  \
            for (int i = 0; i < 2; i++)                                        \
                cpa16(st + DN_B_OFF + stoffB[i], Bg + (long)i*32*INTER + k0);  \
        }                                                                      \
        CP_COMMIT();                                                           \
        const uint32_t As = sb + (SS)*DN_STAGE_B;                              \
        const uint32_t Bs = As + DN_B_OFF;                                     \
        _Pragma("unroll")                                                      \
        for (int ks = 0; ks < 4; ks++) {                                       \
            uint32_t af[4][4], bf[4];                                          \
            _Pragma("unroll")                                                  \
            for (int mi = 0; mi < 4; mi++)                                     \
                ldsm4(af[mi], As + browA + mi*2048 + akb_r[ks]);               \
            ldsm4(bf, Bs + browB + bkb_r[ks]);                                 \
            _Pragma("unroll")                                                  \
            for (int mi = 0; mi < 4; mi++)                                     \
                _Pragma("unroll")                                              \
                for (int ni = 0; ni < 2; ni++)                                 \
                    mma_f16(acc[mi][ni], af[mi][0], af[mi][1], af[mi][2],      \
                            af[mi][3], bf[ni*2], bf[ni*2+1]);                  \
        }                                                                      \
        j++;                                                                   \
    }

    {
        int j = 0;
        while (j + 3 <= nK) { DN_BODY(0); DN_BODY(1); DN_BODY(2); }
        // nK % 3 == 2 tail (86 = 3*28 + 2), enters with j % 3 == 0
        DN_BODY(0); DN_BODY(1);
    }
#undef DN_BODY

#pragma unroll
    for (int mi = 0; mi < 4; mi++) {
#pragma unroll
        for (int ni = 0; ni < 2; ni++) {
            long r0 = bm + wm*64 + mi*16 + grp;
            long c0 = bn + wn*16 + ni*8 + tig*2;
            *(float2*)(C + r0*HID + c0)     = make_float2(acc[mi][ni][0], acc[mi][ni][1]);
            *(float2*)(C + (r0+8)*HID + c0) = make_float2(acc[mi][ni][2], acc[mi][ni][3]);
        }
    }
}

// ---------------- elementwise / reductions ----------------
__global__ void cvt_h_kernel(const float4* __restrict__ in, __half2* __restrict__ out, long n4){
    long i = (long)blockIdx.x * blockDim.x + threadIdx.x;
    if (i >= n4) return;
    float4 v = in[i];
    out[2*i]   = __floats2half2_rn(v.x, v.y);
    out[2*i+1] = __floats2half2_rn(v.z, v.w);
}

__global__ void rowsq_kernel(const float* __restrict__ wup, float* __restrict__ out){
    int row  = blockIdx.x * 8 + (threadIdx.x >> 5);
    int lane = threadIdx.x & 31;
    if (row >= INTER) return;
    const float4* p = (const float4*)(wup + (long)row * HID);
    float s = 0.f;
#pragma unroll 4
    for (int j = lane; j < HID/4; j += 32) {
        float4 v = p[j];
        s += v.x*v.x + v.y*v.y + v.z*v.z + v.w*v.w;
    }
#pragma unroll
    for (int off = 16; off > 0; off >>= 1) s += __shfl_xor_sync(0xffffffffu, s, off);
    if (lane == 0) out[row] = s;
}

__global__ void impacts_final(const float* __restrict__ spart, const float* __restrict__ rowsq,
                              float* __restrict__ out){
    int idx = blockIdx.x * 256 + threadIdx.x;
    if (idx >= BATCH * INTER) return;
    int i = idx % INTER;
    out[idx] = sqrtf(spart[idx] * rowsq[i]);
}

// ---------------- launch ----------------
extern "C" void kernel_launch(void* const* d_in, const int* in_sizes, int n_in,
                              void* d_out, int out_size)
{
    const float* X  = (const float*)d_in[0];
    const float* Wg = (const float*)d_in[1];
    const float* Wu = (const float*)d_in[2];
    const float* Wd = (const float*)d_in[3];
    float* out = (float*)d_out;

    __half *Xh, *Wgh, *Wuh, *Wdh, *inter;
    float *rsq, *spart;
    cudaGetSymbolAddress((void**)&Xh,  g_Xh);
    cudaGetSymbolAddress((void**)&Wgh, g_Wgh);
    cudaGetSymbolAddress((void**)&Wuh, g_Wuh);
    cudaGetSymbolAddress((void**)&Wdh, g_Wdh);
    cudaGetSymbolAddress((void**)&inter, g_inter);
    cudaGetSymbolAddress((void**)&rsq, g_rowsq);
    cudaGetSymbolAddress((void**)&spart, g_s);

    cudaFuncSetAttribute(gemm_gu,   cudaFuncAttributeMaxDynamicSharedMemorySize, GU_SMEM_BYTES);
    cudaFuncSetAttribute(gemm_down, cudaFuncAttributeMaxDynamicSharedMemorySize, DN_SMEM_BYTES);

    long nX = (long)MTOK * HID / 4, nW = (long)INTER * HID / 4;

    // zero impacts accumulator (memset node; graph-capturable)
    cudaMemsetAsync(spart, 0, BATCH*INTER*sizeof(float));

    cvt_h_kernel<<<(unsigned)((nX + 255)/256), 256>>>((const float4*)X,  (__half2*)Xh,  nX);
    cvt_h_kernel<<<(unsigned)((nW + 255)/256), 256>>>((const float4*)Wg, (__half2*)Wgh, nW);
    cvt_h_kernel<<<(unsigned)((nW + 255)/256), 256>>>((const float4*)Wu, (__half2*)Wuh, nW);

    // kernel-launch #4 (ncu capture target)
    gemm_gu<<<(INTER/64)*(MTOK/128), 256, GU_SMEM_BYTES>>>(Xh, Wgh, Wuh, inter, spart);

    cvt_h_kernel<<<(unsigned)((nW + 255)/256), 256>>>((const float4*)Wd, (__half2*)Wdh, nW);

    rowsq_kernel<<<(INTER + 7)/8, 256>>>(Wu, rsq);
    impacts_final<<<(BATCH*INTER + 255)/256, 256>>>(spart, rsq, out + OUT_ELEMS);

    gemm_down<<<(HID/64)*(MTOK/128), 256, DN_SMEM_BYTES>>>(inter, Wdh, out);
}

// round 12
// speedup vs baseline: 1.1153x; 1.1153x over previous
#include <cuda_runtime.h>
#include <cuda_fp16.h>
#include <cstdint>
#include <math.h>

#define BATCH 4
#define SEQ   2048
#define HID   2048
#define INTER 5504
#define MTOK  (BATCH*SEQ)            // 8192
#define OUT_ELEMS ((long)MTOK*HID)   // 16777216

// ---------------- scratch ----------------
__device__ __half g_Xh [(long)MTOK*HID];
__device__ __half g_Wgh[(long)INTER*HID];
__device__ __half g_Wuh[(long)INTER*HID];
__device__ __half g_Wdh[(long)HID*INTER];
__device__ __half g_inter[(long)MTOK*INTER];
__device__ float  g_rowsq[INTER];
__device__ float  g_s[BATCH*INTER];      // impacts accumulator (atomicAdd)

// ---------------- helpers ----------------
__device__ __forceinline__ uint32_t smem_u32(const void* p){
    uint32_t a;
    asm("{ .reg .u64 t; cvta.to.shared.u64 t, %1; cvt.u32.u64 %0, t; }" : "=r"(a) : "l"(p));
    return a;
}
__device__ __forceinline__ void cpa16(uint32_t dst, const void* src){
    asm volatile("cp.async.cg.shared.global [%0], [%1], 16;" :: "r"(dst), "l"(src));
}
__device__ __forceinline__ void ldsm4(uint32_t r[4], uint32_t addr){
    asm volatile("ldmatrix.sync.aligned.m8n8.x4.shared.b16 {%0,%1,%2,%3}, [%4];"
                 : "=r"(r[0]), "=r"(r[1]), "=r"(r[2]), "=r"(r[3]) : "r"(addr));
}
__device__ __forceinline__ void mma_f16(float c[4],
                                        uint32_t a0, uint32_t a1, uint32_t a2, uint32_t a3,
                                        uint32_t b0, uint32_t b1) {
    asm volatile(
        "mma.sync.aligned.m16n8k16.row.col.f32.f16.f16.f32 "
        "{%0,%1,%2,%3}, {%4,%5,%6,%7}, {%8,%9}, {%0,%1,%2,%3};"
        : "+f"(c[0]), "+f"(c[1]), "+f"(c[2]), "+f"(c[3])
        : "r"(a0), "r"(a1), "r"(a2), "r"(a3), "r"(b0), "r"(b1));
}
#define CP_COMMIT() asm volatile("cp.async.commit_group;" ::: "memory")
#define CP_WAIT(n)  asm volatile("cp.async.wait_group %0;" :: "n"(n) : "memory")

// 128B-row XOR swizzle (conflict-free)
#define SWZB(o) ((o) ^ (((o) >> 3) & 0x70))

// ============================================================================
// Fused gate/up GEMM + SwiGLU + impacts partial reduction.
// Block 128m x 64n, 8 warps (2m x 4n), warp 64m x 16n per mat.
// 3 stages x 32KB = 96KB -> 2 CTAs/SM. Mainloop unrolled by 3.
// ============================================================================
#define GU_STAGE_B 32768
#define GU_BG_OFF  16384
#define GU_BU_OFF  24576
#define GU_SMEM_BYTES (3*GU_STAGE_B)   // 98304

__global__ void __launch_bounds__(256,2)
gemm_gu(const __half* __restrict__ X, const __half* __restrict__ Wg,
        const __half* __restrict__ Wu, __half* __restrict__ inter,
        float* __restrict__ spart)
{
    extern __shared__ char smemc[];
    const uint32_t sb = smem_u32(smemc);

    const int tid  = threadIdx.x;
    const int wid  = tid >> 5;
    const int lane = tid & 31;
    const int grp  = lane >> 2;
    const int tig  = lane & 3;
    const int wm   = wid >> 2;    // 0..1
    const int wn   = wid & 3;     // 0..3

    const int NBN = INTER/64;     // 86
    const int GM  = 16;
    int bid = blockIdx.x;
    int g   = bid / (GM*NBN);
    int r   = bid % (GM*NBN);
    const long bm = (long)(g*GM + (r % GM)) * 128;
    const int  bn = (r / GM) * 64;

    const int ldr = tid >> 3;        // 0..31
    const int ldc = tid & 7;         // 0..7 (16B units)

    const __half* Ag = X  + (bm + ldr)*(long)HID + ldc*8;
    const __half* Gg = Wg + (long)(bn + ldr)*HID + ldc*8;
    const __half* Ug = Wu + (long)(bn + ldr)*HID + ldc*8;

    float acc_g[4][2][4], acc_u[4][2][4];
#pragma unroll
    for (int mi = 0; mi < 4; mi++)
#pragma unroll
        for (int ni = 0; ni < 2; ni++)
#pragma unroll
            for (int q = 0; q < 4; q++) { acc_g[mi][ni][q] = 0.f; acc_u[mi][ni][q] = 0.f; }

    uint32_t stoffA[4];
#pragma unroll
    for (int i = 0; i < 4; i++)
        stoffA[i] = SWZB((uint32_t)((ldr + 32*i)*128 + ldc*16));
    uint32_t stoffB[2];
#pragma unroll
    for (int i = 0; i < 2; i++)
        stoffB[i] = SWZB((uint32_t)((ldr + 32*i)*128 + ldc*16));

    // ldmatrix per-lane geometry (hoisted XOR terms)
    const uint32_t swzm = (lane & 7) * 16;
    const uint32_t browA = (wm*64 + (lane & 15)) * 128;
    const uint32_t akbe = ((lane >> 4) & 1) * 16;
    const uint32_t browB = (wn*16 + ((lane >> 4) & 1)*8 + (lane & 7)) * 128;
    const uint32_t bkbe = ((lane >> 3) & 1) * 16;
    uint32_t akb_r[4], bkb_r[4];
#pragma unroll
    for (int ks = 0; ks < 4; ks++) {
        akb_r[ks] = ((uint32_t)(ks*32) + akbe) ^ swzm;
        bkb_r[ks] = ((uint32_t)(ks*32) + bkbe) ^ swzm;
    }

    const int nK = HID/64;   // 32

    // preload chunks 0,1 into stages 0,1
#pragma unroll
    for (int p = 0; p < 2; p++) {
        const int k0 = p*64;
        const uint32_t st = sb + p*GU_STAGE_B;
#pragma unroll
        for (int i = 0; i < 4; i++)
            cpa16(st + stoffA[i], Ag + (long)i*32*HID + k0);
#pragma unroll
        for (int i = 0; i < 2; i++) {
            cpa16(st + GU_BG_OFF + stoffB[i], Gg + (long)i*32*HID + k0);
            cpa16(st + GU_BU_OFF + stoffB[i], Ug + (long)i*32*HID + k0);
        }
        CP_COMMIT();
    }

#define GU_BODY(SS)                                                            \
    {                                                                          \
        CP_WAIT(1);                                                            \
        __syncthreads();                                                       \
        if (j + 2 < nK) {                                                      \
            const int k0 = (j+2)*64;                                           \
            const uint32_t st = sb + (((SS)+2)%3)*GU_STAGE_B;                  \
            _Pragma("unroll")                                                  \
            for (int i = 0; i < 4; i++)                                        \
                cpa16(st + stoffA[i], Ag + (long)i*32*HID + k0);               \
            _Pragma("unroll")                                                  \
            for (int i = 0; i < 2; i++) {                                      \
                cpa16(st + GU_BG_OFF + stoffB[i], Gg + (long)i*32*HID + k0);   \
                cpa16(st + GU_BU_OFF + stoffB[i], Ug + (long)i*32*HID + k0);   \
            }                                                                  \
        }                                                                      \
        CP_COMMIT();                                                           \
        const uint32_t As = sb + (SS)*GU_STAGE_B;                              \
        const uint32_t Gs = As + GU_BG_OFF;                                    \
        const uint32_t Us = As + GU_BU_OFF;                                    \
        _Pragma("unroll")                                                      \
        for (int ks = 0; ks < 4; ks++) {                                       \
            uint32_t af[4][4], bg[4], bu[4];                                   \
            _Pragma("unroll")                                                  \
            for (int mi = 0; mi < 4; mi++)                                     \
                ldsm4(af[mi], As + browA + mi*2048 + akb_r[ks]);               \
            ldsm4(bg, Gs + browB + bkb_r[ks]);                                 \
            ldsm4(bu, Us + browB + bkb_r[ks]);                                 \
            _Pragma("unroll")                                                  \
            for (int mi = 0; mi < 4; mi++)                                     \
                _Pragma("unroll")                                              \
                for (int ni = 0; ni < 2; ni++) {                               \
                    mma_f16(acc_g[mi][ni], af[mi][0], af[mi][1], af[mi][2],    \
                            af[mi][3], bg[ni*2], bg[ni*2+1]);                  \
                    mma_f16(acc_u[mi][ni], af[mi][0], af[mi][1], af[mi][2],    \
                            af[mi][3], bu[ni*2], bu[ni*2+1]);                  \
                }                                                              \
        }                                                                      \
        j++;                                                                   \
    }

    {
        int j = 0;
        while (j + 3 <= nK) { GU_BODY(0); GU_BODY(1); GU_BODY(2); }
        // nK % 3 == 2 tail (32 = 3*10 + 2), enters with j % 3 == 0
        GU_BODY(0); GU_BODY(1);
    }
#undef GU_BODY

    // epilogue: inter = half( silu(g) * u );  colsum += o^2 for impacts
    float cs[2][2] = {{0.f,0.f},{0.f,0.f}};   // [ni][col in pair]
#pragma unroll
    for (int mi = 0; mi < 4; mi++) {
#pragma unroll
        for (int ni = 0; ni < 2; ni++) {
            long r0 = bm + wm*64 + mi*16 + grp;
            long c0 = bn + wn*16 + ni*8 + tig*2;
            float gv, uv; __half2 h;
            gv = acc_g[mi][ni][0]; uv = acc_u[mi][ni][0];
            float o0 = (gv / (1.f + __expf(-gv))) * uv;
            gv = acc_g[mi][ni][1]; uv = acc_u[mi][ni][1];
            float o1 = (gv / (1.f + __expf(-gv))) * uv;
            h = __floats2half2_rn(o0, o1);
            *(__half2*)(inter + r0*INTER + c0) = h;
            gv = acc_g[mi][ni][2]; uv = acc_u[mi][ni][2];
            float o2 = (gv / (1.f + __expf(-gv))) * uv;
            gv = acc_g[mi][ni][3]; uv = acc_u[mi][ni][3];
            float o3 = (gv / (1.f + __expf(-gv))) * uv;
            h = __floats2half2_rn(o2, o3);
            *(__half2*)(inter + (r0+8)*INTER + c0) = h;
            cs[ni][0] += o0*o0 + o2*o2;
            cs[ni][1] += o1*o1 + o3*o3;
        }
    }
    // reduce over the 8 row-lane-groups (lanes differing in bits 2..4)
#pragma unroll
    for (int off = 4; off < 32; off <<= 1) {
#pragma unroll
        for (int ni = 0; ni < 2; ni++) {
            cs[ni][0] += __shfl_xor_sync(0xffffffffu, cs[ni][0], off);
            cs[ni][1] += __shfl_xor_sync(0xffffffffu, cs[ni][1], off);
        }
    }
    if (grp == 0) {
        const int b = (int)(bm >> 11);          // bm / SEQ
        float* sp = spart + b*INTER;
#pragma unroll
        for (int ni = 0; ni < 2; ni++) {
            int c0 = bn + wn*16 + ni*8 + tig*2;
            atomicAdd(&sp[c0],   cs[ni][0]);
            atomicAdd(&sp[c0+1], cs[ni][1]);
        }
    }
}

// ============================================================================
// Down GEMM fp16 + ldmatrix (R10-proven): out = inter * Wd^T, K=5504.
// Block 128x128, warp 64x32; 3 stages x 32KB = 96KB -> 2 CTAs/SM.
// Mainloop unrolled by 3.
// ============================================================================
#define DN_STAGE_B 32768
#define DN_B_OFF   16384
#define DN_SMEM_BYTES (3*DN_STAGE_B)   // 98304

__global__ void __launch_bounds__(256,2)
gemm_down(const __half* __restrict__ A, const __half* __restrict__ B, float* __restrict__ C)
{
    extern __shared__ char smemc[];
    const uint32_t sb = smem_u32(smemc);

    const int tid  = threadIdx.x;
    const int wid  = tid >> 5;
    const int lane = tid & 31;
    const int grp  = lane >> 2;
    const int tig  = lane & 3;
    const int wm   = wid >> 2;
    const int wn   = wid & 3;

    const int NBN = HID/128;   // 16
    const int GM  = 16;
    int bid = blockIdx.x;
    int g   = bid / (GM*NBN);
    int r   = bid % (GM*NBN);
    const long bm = (long)(g*GM + (r % GM)) * 128;
    const int  bn = (r / GM) * 128;

    const int ldr = tid >> 3;
    const int ldc = tid & 7;

    const __half* Ag = A + (bm + ldr)*(long)INTER + ldc*8;
    const __half* Bg = B + (long)(bn + ldr)*INTER + ldc*8;

    float acc[4][4][4];
#pragma unroll
    for (int mi = 0; mi < 4; mi++)
#pragma unroll
        for (int ni = 0; ni < 4; ni++)
#pragma unroll
            for (int q = 0; q < 4; q++) acc[mi][ni][q] = 0.f;

    uint32_t stoff[4];
#pragma unroll
    for (int i = 0; i < 4; i++)
        stoff[i] = SWZB((uint32_t)((ldr + 32*i)*128 + ldc*16));

    const uint32_t swzm = (lane & 7) * 16;
    const uint32_t browA = (wm*64 + (lane & 15)) * 128;
    const uint32_t akbe = ((lane >> 4) & 1) * 16;
    const uint32_t browB = (wn*32 + ((lane >> 4) & 1)*8 + (lane & 7)) * 128;
    const uint32_t bkbe = ((lane >> 3) & 1) * 16;
    uint32_t akb_r[4], bkb_r[4];
#pragma unroll
    for (int ks = 0; ks < 4; ks++) {
        akb_r[ks] = ((uint32_t)(ks*32) + akbe) ^ swzm;
        bkb_r[ks] = ((uint32_t)(ks*32) + bkbe) ^ swzm;
    }

    const int nK = INTER/64;   // 86

#pragma unroll
    for (int p = 0; p < 2; p++) {
        const int k0 = p*64;
        const uint32_t st = sb + p*DN_STAGE_B;
#pragma unroll
        for (int i = 0; i < 4; i++) {
            cpa16(st + stoff[i],            Ag + (long)i*32*INTER + k0);
            cpa16(st + DN_B_OFF + stoff[i], Bg + (long)i*32*INTER + k0);
        }
        CP_COMMIT();
    }

#define DN_BODY(SS)                                                            \
    {                                                                          \
        CP_WAIT(1);                                                            \
        __syncthreads();                                                       \
        if (j + 2 < nK) {                                                      \
            const int k0 = (j+2)*64;                                           \
            const uint32_t st = sb + (((SS)+2)%3)*DN_STAGE_B;                  \
            _Pragma("unroll")                                                  \
            for (int i = 0; i < 4; i++) {                                      \
                cpa16(st + stoff[i],            Ag + (long)i*32*INTER + k0);   \
                cpa16(st + DN_B_OFF + stoff[i], Bg + (long)i*32*INTER + k0);   \
            }                                                                  \
        }                                                                      \
        CP_COMMIT();                                                           \
        const uint32_t As = sb + (SS)*DN_STAGE_B;                              \
        const uint32_t Bs = As + DN_B_OFF;                                     \
        _Pragma("unroll")                                                      \
        for (int ks = 0; ks < 4; ks++) {                                       \
            uint32_t af[4][4], bf0[4], bf1[4];                                 \
            _Pragma("unroll")                                                  \
            for (int mi = 0; mi < 4; mi++)                                     \
                ldsm4(af[mi], As + browA + mi*2048 + akb_r[ks]);               \
            ldsm4(bf0, Bs + browB + bkb_r[ks]);                                \
            ldsm4(bf1, Bs + browB + 16*128 + bkb_r[ks]);                       \
            _Pragma("unroll")                                                  \
            for (int mi = 0; mi < 4; mi++) {                                   \
                _Pragma("unroll")                                              \
                for (int ni = 0; ni < 2; ni++)                                 \
                    mma_f16(acc[mi][ni], af[mi][0], af[mi][1], af[mi][2],      \
                            af[mi][3], bf0[ni*2], bf0[ni*2+1]);                \
                _Pragma("unroll")                                              \
                for (int ni = 0; ni < 2; ni++)                                 \
                    mma_f16(acc[mi][2+ni], af[mi][0], af[mi][1], af[mi][2],    \
                            af[mi][3], bf1[ni*2], bf1[ni*2+1]);                \
            }                                                                  \
        }                                                                      \
        j++;                                                                   \
    }

    {
        int j = 0;
        while (j + 3 <= nK) { DN_BODY(0); DN_BODY(1); DN_BODY(2); }
        // nK % 3 == 2 tail (86 = 3*28 + 2), enters with j % 3 == 0
        DN_BODY(0); DN_BODY(1);
    }
#undef DN_BODY

#pragma unroll
    for (int mi = 0; mi < 4; mi++) {
#pragma unroll
        for (int ni = 0; ni < 4; ni++) {
            long r0 = bm + wm*64 + mi*16 + grp;
            long c0 = bn + wn*32 + ni*8 + tig*2;
            *(float2*)(C + r0*HID + c0)     = make_float2(acc[mi][ni][0], acc[mi][ni][1]);
            *(float2*)(C + (r0+8)*HID + c0) = make_float2(acc[mi][ni][2], acc[mi][ni][3]);
        }
    }
}

// ---------------- elementwise / reductions ----------------
__global__ void cvt_h_kernel(const float4* __restrict__ in, __half2* __restrict__ out, long n4){
    long i = (long)blockIdx.x * blockDim.x + threadIdx.x;
    if (i >= n4) return;
    float4 v = in[i];
    out[2*i]   = __floats2half2_rn(v.x, v.y);
    out[2*i+1] = __floats2half2_rn(v.z, v.w);
}

__global__ void rowsq_kernel(const float* __restrict__ wup, float* __restrict__ out){
    int row  = blockIdx.x * 8 + (threadIdx.x >> 5);
    int lane = threadIdx.x & 31;
    if (row >= INTER) return;
    const float4* p = (const float4*)(wup + (long)row * HID);
    float s = 0.f;
#pragma unroll 4
    for (int j = lane; j < HID/4; j += 32) {
        float4 v = p[j];
        s += v.x*v.x + v.y*v.y + v.z*v.z + v.w*v.w;
    }
#pragma unroll
    for (int off = 16; off > 0; off >>= 1) s += __shfl_xor_sync(0xffffffffu, s, off);
    if (lane == 0) out[row] = s;
}

__global__ void impacts_final(const float* __restrict__ spart, const float* __restrict__ rowsq,
                              float* __restrict__ out){
    int idx = blockIdx.x * 256 + threadIdx.x;
    if (idx >= BATCH * INTER) return;
    int i = idx % INTER;
    out[idx] = sqrtf(spart[idx] * rowsq[i]);
}

// ---------------- launch ----------------
extern "C" void kernel_launch(void* const* d_in, const int* in_sizes, int n_in,
                              void* d_out, int out_size)
{
    const float* X  = (const float*)d_in[0];
    const float* Wg = (const float*)d_in[1];
    const float* Wu = (const float*)d_in[2];
    const float* Wd = (const float*)d_in[3];
    float* out = (float*)d_out;

    __half *Xh, *Wgh, *Wuh, *Wdh, *inter;
    float *rsq, *spart;
    cudaGetSymbolAddress((void**)&Xh,  g_Xh);
    cudaGetSymbolAddress((void**)&Wgh, g_Wgh);
    cudaGetSymbolAddress((void**)&Wuh, g_Wuh);
    cudaGetSymbolAddress((void**)&Wdh, g_Wdh);
    cudaGetSymbolAddress((void**)&inter, g_inter);
    cudaGetSymbolAddress((void**)&rsq, g_rowsq);
    cudaGetSymbolAddress((void**)&spart, g_s);

    cudaFuncSetAttribute(gemm_gu,   cudaFuncAttributeMaxDynamicSharedMemorySize, GU_SMEM_BYTES);
    cudaFuncSetAttribute(gemm_down, cudaFuncAttributeMaxDynamicSharedMemorySize, DN_SMEM_BYTES);

    long nX = (long)MTOK * HID / 4, nW = (long)INTER * HID / 4;

    // zero impacts accumulator (memset node; graph-capturable)
    cudaMemsetAsync(spart, 0, BATCH*INTER*sizeof(float));

    cvt_h_kernel<<<(unsigned)((nX + 255)/256), 256>>>((const float4*)X,  (__half2*)Xh,  nX);
    cvt_h_kernel<<<(unsigned)((nW + 255)/256), 256>>>((const float4*)Wg, (__half2*)Wgh, nW);
    cvt_h_kernel<<<(unsigned)((nW + 255)/256), 256>>>((const float4*)Wu, (__half2*)Wuh, nW);

    // kernel-launch #4 (ncu capture target)
    gemm_gu<<<(INTER/64)*(MTOK/128), 256, GU_SMEM_BYTES>>>(Xh, Wgh, Wuh, inter, spart);

    // off-critical-path small work right after gu
    rowsq_kernel<<<(INTER + 7)/8, 256>>>(Wu, rsq);
    impacts_final<<<(BATCH*INTER + 255)/256, 256>>>(spart, rsq, out + OUT_ELEMS);

    cvt_h_kernel<<<(unsigned)((nW + 255)/256), 256>>>((const float4*)Wd, (__half2*)Wdh, nW);

    gemm_down<<<(HID/128)*(MTOK/128), 256, DN_SMEM_BYTES>>>(inter, Wdh, out);
}

// round 13
// speedup vs baseline: 1.1249x; 1.0086x over previous
#include <cuda_runtime.h>
#include <cuda_fp16.h>
#include <cstdint>
#include <math.h>

#define BATCH 4
#define SEQ   2048
#define HID   2048
#define INTER 5504
#define MTOK  (BATCH*SEQ)            // 8192
#define OUT_ELEMS ((long)MTOK*HID)   // 16777216

// ---------------- scratch ----------------
__device__ __half g_Xh [(long)MTOK*HID];
__device__ __half g_Wgh[(long)INTER*HID];
__device__ __half g_Wuh[(long)INTER*HID];
__device__ __half g_Wdh[(long)HID*INTER];
__device__ __half g_inter[(long)MTOK*INTER];
__device__ float  g_rowsq[INTER];
__device__ float  g_s[BATCH*INTER];      // impacts accumulator (atomicAdd)

// ---------------- helpers ----------------
__device__ __forceinline__ uint32_t smem_u32(const void* p){
    uint32_t a;
    asm("{ .reg .u64 t; cvta.to.shared.u64 t, %1; cvt.u32.u64 %0, t; }" : "=r"(a) : "l"(p));
    return a;
}
__device__ __forceinline__ void cpa16(uint32_t dst, const void* src){
    asm volatile("cp.async.cg.shared.global [%0], [%1], 16;" :: "r"(dst), "l"(src));
}
__device__ __forceinline__ void ldsm4(uint32_t r[4], uint32_t addr){
    asm volatile("ldmatrix.sync.aligned.m8n8.x4.shared.b16 {%0,%1,%2,%3}, [%4];"
                 : "=r"(r[0]), "=r"(r[1]), "=r"(r[2]), "=r"(r[3]) : "r"(addr));
}
__device__ __forceinline__ void mma_f16(float c[4],
                                        uint32_t a0, uint32_t a1, uint32_t a2, uint32_t a3,
                                        uint32_t b0, uint32_t b1) {
    asm volatile(
        "mma.sync.aligned.m16n8k16.row.col.f32.f16.f16.f32 "
        "{%0,%1,%2,%3}, {%4,%5,%6,%7}, {%8,%9}, {%0,%1,%2,%3};"
        : "+f"(c[0]), "+f"(c[1]), "+f"(c[2]), "+f"(c[3])
        : "r"(a0), "r"(a1), "r"(a2), "r"(a3), "r"(b0), "r"(b1));
}
#define CP_COMMIT() asm volatile("cp.async.commit_group;" ::: "memory")
#define CP_WAIT(n)  asm volatile("cp.async.wait_group %0;" :: "n"(n) : "memory")

// 128B-row XOR swizzle (conflict-free)
#define SWZB(o) ((o) ^ (((o) >> 3) & 0x70))

// ============================================================================
// Fused gate/up GEMM + SwiGLU + impacts partial reduction.
// Block 128m x 64n, 8 warps (2m x 4n), warp 64m x 16n per mat.
// 3 stages x 32KB = 96KB -> 2 CTAs/SM. Mainloop unrolled by 3.
// ============================================================================
#define GU_STAGE_B 32768
#define GU_BG_OFF  16384
#define GU_BU_OFF  24576
#define GU_SMEM_BYTES (3*GU_STAGE_B)   // 98304

__global__ void __launch_bounds__(256,2)
gemm_gu(const __half* __restrict__ X, const __half* __restrict__ Wg,
        const __half* __restrict__ Wu, __half* __restrict__ inter,
        float* __restrict__ spart)
{
    extern __shared__ char smemc[];
    const uint32_t sb = smem_u32(smemc);

    const int tid  = threadIdx.x;
    const int wid  = tid >> 5;
    const int lane = tid & 31;
    const int grp  = lane >> 2;
    const int tig  = lane & 3;
    const int wm   = wid >> 2;    // 0..1
    const int wn   = wid & 3;     // 0..3

    const int NBN = INTER/64;     // 86
    const int GM  = 16;
    int bid = blockIdx.x;
    int g   = bid / (GM*NBN);
    int r   = bid % (GM*NBN);
    const long bm = (long)(g*GM + (r % GM)) * 128;
    const int  bn = (r / GM) * 64;

    const int ldr = tid >> 3;        // 0..31
    const int ldc = tid & 7;         // 0..7 (16B units)

    const __half* Ag = X  + (bm + ldr)*(long)HID + ldc*8;
    const __half* Gg = Wg + (long)(bn + ldr)*HID + ldc*8;
    const __half* Ug = Wu + (long)(bn + ldr)*HID + ldc*8;

    float acc_g[4][2][4], acc_u[4][2][4];
#pragma unroll
    for (int mi = 0; mi < 4; mi++)
#pragma unroll
        for (int ni = 0; ni < 2; ni++)
#pragma unroll
            for (int q = 0; q < 4; q++) { acc_g[mi][ni][q] = 0.f; acc_u[mi][ni][q] = 0.f; }

    uint32_t stoffA[4];
#pragma unroll
    for (int i = 0; i < 4; i++)
        stoffA[i] = SWZB((uint32_t)((ldr + 32*i)*128 + ldc*16));
    uint32_t stoffB[2];
#pragma unroll
    for (int i = 0; i < 2; i++)
        stoffB[i] = SWZB((uint32_t)((ldr + 32*i)*128 + ldc*16));

    // ldmatrix per-lane geometry (hoisted XOR terms)
    const uint32_t swzm = (lane & 7) * 16;
    const uint32_t browA = (wm*64 + (lane & 15)) * 128;
    const uint32_t akbe = ((lane >> 4) & 1) * 16;
    const uint32_t browB = (wn*16 + ((lane >> 4) & 1)*8 + (lane & 7)) * 128;
    const uint32_t bkbe = ((lane >> 3) & 1) * 16;
    uint32_t akb_r[4], bkb_r[4];
#pragma unroll
    for (int ks = 0; ks < 4; ks++) {
        akb_r[ks] = ((uint32_t)(ks*32) + akbe) ^ swzm;
        bkb_r[ks] = ((uint32_t)(ks*32) + bkbe) ^ swzm;
    }

    const int nK = HID/64;   // 32

    // preload chunks 0,1 into stages 0,1
#pragma unroll
    for (int p = 0; p < 2; p++) {
        const int k0 = p*64;
        const uint32_t st = sb + p*GU_STAGE_B;
#pragma unroll
        for (int i = 0; i < 4; i++)
            cpa16(st + stoffA[i], Ag + (long)i*32*HID + k0);
#pragma unroll
        for (int i = 0; i < 2; i++) {
            cpa16(st + GU_BG_OFF + stoffB[i], Gg + (long)i*32*HID + k0);
            cpa16(st + GU_BU_OFF + stoffB[i], Ug + (long)i*32*HID + k0);
        }
        CP_COMMIT();
    }

#define GU_BODY(SS)                                                            \
    {                                                                          \
        CP_WAIT(1);                                                            \
        __syncthreads();                                                       \
        if (j + 2 < nK) {                                                      \
            const int k0 = (j+2)*64;                                           \
            const uint32_t st = sb + (((SS)+2)%3)*GU_STAGE_B;                  \
            _Pragma("unroll")                                                  \
            for (int i = 0; i < 4; i++)                                        \
                cpa16(st + stoffA[i], Ag + (long)i*32*HID + k0);               \
            _Pragma("unroll")                                                  \
            for (int i = 0; i < 2; i++) {                                      \
                cpa16(st + GU_BG_OFF + stoffB[i], Gg + (long)i*32*HID + k0);   \
                cpa16(st + GU_BU_OFF + stoffB[i], Ug + (long)i*32*HID + k0);   \
            }                                                                  \
        }                                                                      \
        CP_COMMIT();                                                           \
        const uint32_t As = sb + (SS)*GU_STAGE_B;                              \
        const uint32_t Gs = As + GU_BG_OFF;                                    \
        const uint32_t Us = As + GU_BU_OFF;                                    \
        _Pragma("unroll")                                                      \
        for (int ks = 0; ks < 4; ks++) {                                       \
            uint32_t af[4][4], bg[4], bu[4];                                   \
            _Pragma("unroll")                                                  \
            for (int mi = 0; mi < 4; mi++)                                     \
                ldsm4(af[mi], As + browA + mi*2048 + akb_r[ks]);               \
            ldsm4(bg, Gs + browB + bkb_r[ks]);                                 \
            ldsm4(bu, Us + browB + bkb_r[ks]);                                 \
            _Pragma("unroll")                                                  \
            for (int mi = 0; mi < 4; mi++)                                     \
                _Pragma("unroll")                                              \
                for (int ni = 0; ni < 2; ni++) {                               \
                    mma_f16(acc_g[mi][ni], af[mi][0], af[mi][1], af[mi][2],    \
                            af[mi][3], bg[ni*2], bg[ni*2+1]);                  \
                    mma_f16(acc_u[mi][ni], af[mi][0], af[mi][1], af[mi][2],    \
                            af[mi][3], bu[ni*2], bu[ni*2+1]);                  \
                }                                                              \
        }                                                                      \
        j++;                                                                   \
    }

    {
        int j = 0;
        while (j + 3 <= nK) { GU_BODY(0); GU_BODY(1); GU_BODY(2); }
        // nK % 3 == 2 tail (32 = 3*10 + 2), enters with j % 3 == 0
        GU_BODY(0); GU_BODY(1);
    }
#undef GU_BODY

    // epilogue: inter = half( silu(g) * u );  colsum += o^2 for impacts
    float cs[2][2] = {{0.f,0.f},{0.f,0.f}};   // [ni][col in pair]
#pragma unroll
    for (int mi = 0; mi < 4; mi++) {
#pragma unroll
        for (int ni = 0; ni < 2; ni++) {
            long r0 = bm + wm*64 + mi*16 + grp;
            long c0 = bn + wn*16 + ni*8 + tig*2;
            float gv, uv; __half2 h;
            gv = acc_g[mi][ni][0]; uv = acc_u[mi][ni][0];
            float o0 = (gv / (1.f + __expf(-gv))) * uv;
            gv = acc_g[mi][ni][1]; uv = acc_u[mi][ni][1];
            float o1 = (gv / (1.f + __expf(-gv))) * uv;
            h = __floats2half2_rn(o0, o1);
            *(__half2*)(inter + r0*INTER + c0) = h;
            gv = acc_g[mi][ni][2]; uv = acc_u[mi][ni][2];
            float o2 = (gv / (1.f + __expf(-gv))) * uv;
            gv = acc_g[mi][ni][3]; uv = acc_u[mi][ni][3];
            float o3 = (gv / (1.f + __expf(-gv))) * uv;
            h = __floats2half2_rn(o2, o3);
            *(__half2*)(inter + (r0+8)*INTER + c0) = h;
            cs[ni][0] += o0*o0 + o2*o2;
            cs[ni][1] += o1*o1 + o3*o3;
        }
    }
    // reduce over the 8 row-lane-groups (lanes differing in bits 2..4)
#pragma unroll
    for (int off = 4; off < 32; off <<= 1) {
#pragma unroll
        for (int ni = 0; ni < 2; ni++) {
            cs[ni][0] += __shfl_xor_sync(0xffffffffu, cs[ni][0], off);
            cs[ni][1] += __shfl_xor_sync(0xffffffffu, cs[ni][1], off);
        }
    }
    if (grp == 0) {
        const int b = (int)(bm >> 11);          // bm / SEQ
        float* sp = spart + b*INTER;
#pragma unroll
        for (int ni = 0; ni < 2; ni++) {
            int c0 = bn + wn*16 + ni*8 + tig*2;
            atomicAdd(&sp[c0],   cs[ni][0]);
            atomicAdd(&sp[c0+1], cs[ni][1]);
        }
    }
}

// ============================================================================
// Down GEMM fp16 + ldmatrix (R10-proven): out = inter * Wd^T, K=5504.
// Block 128x128, warp 64x32; 3 stages x 32KB = 96KB -> 2 CTAs/SM.
// Mainloop unrolled by 3.
// ============================================================================
#define DN_STAGE_B 32768
#define DN_B_OFF   16384
#define DN_SMEM_BYTES (3*DN_STAGE_B)   // 98304

__global__ void __launch_bounds__(256,2)
gemm_down(const __half* __restrict__ A, const __half* __restrict__ B, float* __restrict__ C)
{
    extern __shared__ char smemc[];
    const uint32_t sb = smem_u32(smemc);

    const int tid  = threadIdx.x;
    const int wid  = tid >> 5;
    const int lane = tid & 31;
    const int grp  = lane >> 2;
    const int tig  = lane & 3;
    const int wm   = wid >> 2;
    const int wn   = wid & 3;

    const int NBN = HID/128;   // 16
    const int GM  = 16;
    int bid = blockIdx.x;
    int g   = bid / (GM*NBN);
    int r   = bid % (GM*NBN);
    const long bm = (long)(g*GM + (r % GM)) * 128;
    const int  bn = (r / GM) * 128;

    const int ldr = tid >> 3;
    const int ldc = tid & 7;

    const __half* Ag = A + (bm + ldr)*(long)INTER + ldc*8;
    const __half* Bg = B + (long)(bn + ldr)*INTER + ldc*8;

    float acc[4][4][4];
#pragma unroll
    for (int mi = 0; mi < 4; mi++)
#pragma unroll
        for (int ni = 0; ni < 4; ni++)
#pragma unroll
            for (int q = 0; q < 4; q++) acc[mi][ni][q] = 0.f;

    uint32_t stoff[4];
#pragma unroll
    for (int i = 0; i < 4; i++)
        stoff[i] = SWZB((uint32_t)((ldr + 32*i)*128 + ldc*16));

    const uint32_t swzm = (lane & 7) * 16;
    const uint32_t browA = (wm*64 + (lane & 15)) * 128;
    const uint32_t akbe = ((lane >> 4) & 1) * 16;
    const uint32_t browB = (wn*32 + ((lane >> 4) & 1)*8 + (lane & 7)) * 128;
    const uint32_t bkbe = ((lane >> 3) & 1) * 16;
    uint32_t akb_r[4], bkb_r[4];
#pragma unroll
    for (int ks = 0; ks < 4; ks++) {
        akb_r[ks] = ((uint32_t)(ks*32) + akbe) ^ swzm;
        bkb_r[ks] = ((uint32_t)(ks*32) + bkbe) ^ swzm;
    }

    const int nK = INTER/64;   // 86

#pragma unroll
    for (int p = 0; p < 2; p++) {
        const int k0 = p*64;
        const uint32_t st = sb + p*DN_STAGE_B;
#pragma unroll
        for (int i = 0; i < 4; i++) {
            cpa16(st + stoff[i],            Ag + (long)i*32*INTER + k0);
            cpa16(st + DN_B_OFF + stoff[i], Bg + (long)i*32*INTER + k0);
        }
        CP_COMMIT();
    }

#define DN_BODY(SS)                                                            \
    {                                                                          \
        CP_WAIT(1);                                                            \
        __syncthreads();                                                       \
        if (j + 2 < nK) {                                                      \
            const int k0 = (j+2)*64;                                           \
            const uint32_t st = sb + (((SS)+2)%3)*DN_STAGE_B;                  \
            _Pragma("unroll")                                                  \
            for (int i = 0; i < 4; i++) {                                      \
                cpa16(st + stoff[i],            Ag + (long)i*32*INTER + k0);   \
                cpa16(st + DN_B_OFF + stoff[i], Bg + (long)i*32*INTER + k0);   \
            }                                                                  \
        }                                                                      \
        CP_COMMIT();                                                           \
        const uint32_t As = sb + (SS)*DN_STAGE_B;                              \
        const uint32_t Bs = As + DN_B_OFF;                                     \
        _Pragma("unroll")                                                      \
        for (int ks = 0; ks < 4; ks++) {                                       \
            uint32_t af[4][4], bf0[4], bf1[4];                                 \
            _Pragma("unroll")                                                  \
            for (int mi = 0; mi < 4; mi++)                                     \
                ldsm4(af[mi], As + browA + mi*2048 + akb_r[ks]);               \
            ldsm4(bf0, Bs + browB + bkb_r[ks]);                                \
            ldsm4(bf1, Bs + browB + 16*128 + bkb_r[ks]);                       \
            _Pragma("unroll")                                                  \
            for (int mi = 0; mi < 4; mi++) {                                   \
                _Pragma("unroll")                                              \
                for (int ni = 0; ni < 2; ni++)                                 \
                    mma_f16(acc[mi][ni], af[mi][0], af[mi][1], af[mi][2],      \
                            af[mi][3], bf0[ni*2], bf0[ni*2+1]);                \
                _Pragma("unroll")                                              \
                for (int ni = 0; ni < 2; ni++)                                 \
                    mma_f16(acc[mi][2+ni], af[mi][0], af[mi][1], af[mi][2],    \
                            af[mi][3], bf1[ni*2], bf1[ni*2+1]);                \
            }                                                                  \
        }                                                                      \
        j++;                                                                   \
    }

    {
        int j = 0;
        while (j + 3 <= nK) { DN_BODY(0); DN_BODY(1); DN_BODY(2); }
        // nK % 3 == 2 tail (86 = 3*28 + 2), enters with j % 3 == 0
        DN_BODY(0); DN_BODY(1);
    }
#undef DN_BODY

#pragma unroll
    for (int mi = 0; mi < 4; mi++) {
#pragma unroll
        for (int ni = 0; ni < 4; ni++) {
            long r0 = bm + wm*64 + mi*16 + grp;
            long c0 = bn + wn*32 + ni*8 + tig*2;
            *(float2*)(C + r0*HID + c0)     = make_float2(acc[mi][ni][0], acc[mi][ni][1]);
            *(float2*)(C + (r0+8)*HID + c0) = make_float2(acc[mi][ni][2], acc[mi][ni][3]);
        }
    }
}

// ============================================================================
// Fused conversion: X, Wg, Wu, Wd fp32 -> fp16 in ONE grid.
// Wu range additionally computes rowsq via warp-reduce + atomicAdd
// (each warp = 128 consecutive floats = exactly 1/16 of one 2048-elem row).
// Range boundaries are multiples of 256 float4s -> branch uniform per block.
// ============================================================================
#define NX4 ((long)MTOK*HID/4)      // 4194304
#define NW4 ((long)INTER*HID/4)     // 2818048

__global__ void __launch_bounds__(256)
cvt_all(const float4* __restrict__ X,  const float4* __restrict__ Wg,
        const float4* __restrict__ Wu, const float4* __restrict__ Wd,
        __half2* __restrict__ Xh, __half2* __restrict__ Wgh,
        __half2* __restrict__ Wuh, __half2* __restrict__ Wdh,
        float* __restrict__ rowsq)
{
    long i = (long)blockIdx.x * 256 + threadIdx.x;
    const float4* src;
    __half2* dst;
    bool is_wu = false;
    if (i < NX4)                  { src = X;  dst = Xh; }
    else if (i < NX4 + NW4)       { src = Wg; dst = Wgh; i -= NX4; }
    else if (i < NX4 + 2*NW4)     { src = Wu; dst = Wuh; i -= NX4 + NW4; is_wu = true; }
    else                          { src = Wd; dst = Wdh; i -= NX4 + 2*NW4; }

    float4 v = src[i];
    dst[2*i]   = __floats2half2_rn(v.x, v.y);
    dst[2*i+1] = __floats2half2_rn(v.z, v.w);

    if (is_wu) {
        float s = v.x*v.x + v.y*v.y + v.z*v.z + v.w*v.w;
#pragma unroll
        for (int off = 16; off > 0; off >>= 1)
            s += __shfl_xor_sync(0xffffffffu, s, off);
        if ((threadIdx.x & 31) == 0) {
            int row = (int)(i >> 9);          // i*4 / 2048
            atomicAdd(&rowsq[row], s);
        }
    }
}

__global__ void impacts_final(const float* __restrict__ spart, const float* __restrict__ rowsq,
                              float* __restrict__ out){
    int idx = blockIdx.x * 256 + threadIdx.x;
    if (idx >= BATCH * INTER) return;
    int i = idx % INTER;
    out[idx] = sqrtf(spart[idx] * rowsq[i]);
}

// ---------------- launch ----------------
extern "C" void kernel_launch(void* const* d_in, const int* in_sizes, int n_in,
                              void* d_out, int out_size)
{
    const float* X  = (const float*)d_in[0];
    const float* Wg = (const float*)d_in[1];
    const float* Wu = (const float*)d_in[2];
    const float* Wd = (const float*)d_in[3];
    float* out = (float*)d_out;

    __half *Xh, *Wgh, *Wuh, *Wdh, *inter;
    float *rsq, *spart;
    cudaGetSymbolAddress((void**)&Xh,  g_Xh);
    cudaGetSymbolAddress((void**)&Wgh, g_Wgh);
    cudaGetSymbolAddress((void**)&Wuh, g_Wuh);
    cudaGetSymbolAddress((void**)&Wdh, g_Wdh);
    cudaGetSymbolAddress((void**)&inter, g_inter);
    cudaGetSymbolAddress((void**)&rsq, g_rowsq);
    cudaGetSymbolAddress((void**)&spart, g_s);

    cudaFuncSetAttribute(gemm_gu,   cudaFuncAttributeMaxDynamicSharedMemorySize, GU_SMEM_BYTES);
    cudaFuncSetAttribute(gemm_down, cudaFuncAttributeMaxDynamicSharedMemorySize, DN_SMEM_BYTES);

    // zero accumulators (memset nodes; graph-capturable)
    cudaMemsetAsync(spart, 0, BATCH*INTER*sizeof(float));
    cudaMemsetAsync(rsq,   0, INTER*sizeof(float));

    // one fused conversion pass (also produces rowsq)
    long total4 = NX4 + 3*NW4;                 // 12648448, multiple of 256
    cvt_all<<<(unsigned)(total4/256), 256>>>(
        (const float4*)X, (const float4*)Wg, (const float4*)Wu, (const float4*)Wd,
        (__half2*)Xh, (__half2*)Wgh, (__half2*)Wuh, (__half2*)Wdh, rsq);

    // fused gate/up + SwiGLU + impacts partials
    gemm_gu<<<(INTER/64)*(MTOK/128), 256, GU_SMEM_BYTES>>>(Xh, Wgh, Wuh, inter, spart);

    impacts_final<<<(BATCH*INTER + 255)/256, 256>>>(spart, rsq, out + OUT_ELEMS);

    // down projection
    gemm_down<<<(HID/128)*(MTOK/128), 256, DN_SMEM_BYTES>>>(inter, Wdh, out);
}